// round 15
// baseline (speedup 1.0000x reference)
#include <cuda_runtime.h>
#include <cstdint>
#include <cstddef>

// x:   [B=8192, F=32, E=64] f32
// W:   [E=64, E=64] f32
// out: [B, P=496, E=64] f32,  out[b,p,:] = (x[b,i_p,:] @ W) * x[b,j_p,:]
// (i_p, j_p) = triu_indices(32, k=1), row-major pair order.
//
// R13 locked structure (166.2us kernel / 170.0us e2e, HBM 6301 GB/s) with
// ONE change: __stcs -> __stwt (write-through) on the output stream.
// Final store-policy A/B: .cs and write-back both measured ~6.3 TB/s; .wt
// is the only untested cache operator for this write-once stream.

#define BB 8192
#define FF 32
#define EE 64
#define PP 496
#define NV4 (PP * (EE/4)) // 7936 float4 per batch row
#define NTHREADS 256
#define ROWS_PER_BLK 2

// pairs before row i: sum_{t<i} (31-t) = 31*i - i*(i-1)/2
__device__ __forceinline__ int rowstart(int i) {
    return 31 * i - (i * (i - 1)) / 2;
}

__device__ __forceinline__ float4 fmul4(float4 a, float4 c) {
    float4 r;
    r.x = a.x * c.x; r.y = a.y * c.y; r.z = a.z * c.z; r.w = a.w * c.w;
    return r;
}

// Store one batch row: 16 groups of 16 lanes; group g owns rows i1=g
// (pairs j=g+1..31) and i2=30-g (pairs j=31-g..31); g==15 owns only row 15.
// Interleaved, fully unrolled dual streams: up to two independent
// LDS.128+STG.128 pairs per step -> deep store MLP, no loop-carried
// issue dependency. Group writes are sequential 256B pair records.
__device__ __forceinline__ void store_rows(const float4* __restrict__ xw4,
                                           const float4* __restrict__ xs4,
                                           float4* __restrict__ og,
                                           int g, int v)
{
    const int i1 = g;
    const int i2 = 30 - g;                   // g==15 -> i2==i1 (masked below)
    const bool two = (g < 15);

    const float4 a1 = xw4[i1 * 16 + v];
    const float4 a2 = xw4[i2 * 16 + v];

    float4* o1 = og + (ptrdiff_t)(rowstart(i1) - i1 - 1) * 16 + v;
    float4* o2 = og + (ptrdiff_t)(rowstart(i2) - i2 - 1) * 16 + v;

    #pragma unroll
    for (int j = 1; j < FF; ++j) {
        if (j > i1) {
            const float4 c = xs4[j * 16 + v];
            __stwt(o1 + j * 16, fmul4(a1, c));   // write-through A/B
        }
        if (two && j > i2) {
            const float4 c = xs4[j * 16 + v];
            __stwt(o2 + j * 16, fmul4(a2, c));
        }
    }
}

__global__ __launch_bounds__(NTHREADS)
void bilinear_kernel(const float* __restrict__ x,
                     const float* __restrict__ W,
                     float* __restrict__ out)
{
    // 48 KB smem; dedicated xw buffer -> single barrier between compute and
    // store. Measured: any occupancy >= ~25% saturates the HBM write stream.
    __shared__ float xs[ROWS_PER_BLK * FF * EE]; // 16 KB : x[b0], x[b0+1]
    __shared__ float ws[EE * EE];                // 16 KB : W
    __shared__ float xw[ROWS_PER_BLK * FF * EE]; // 16 KB : xw[0], xw[1]

    const int tid = threadIdx.x;
    const int b0  = blockIdx.x * ROWS_PER_BLK;

    // ---- load x rows (1024 float4) and W (1024 float4) into SMEM ----
    {
        const float4* xg = reinterpret_cast<const float4*>(x) + (size_t)b0 * (FF * EE / 4);
        float4* xs4 = reinterpret_cast<float4*>(xs);
        #pragma unroll
        for (int q = tid; q < ROWS_PER_BLK * FF * EE / 4; q += NTHREADS)
            xs4[q] = xg[q];

        const float4* wg = reinterpret_cast<const float4*>(W);
        float4* ws4 = reinterpret_cast<float4*>(ws);
        #pragma unroll
        for (int q = tid; q < EE * EE / 4; q += NTHREADS)
            ws4[q] = wg[q];
    }

    __syncthreads();

    // ---- matmul: xw[r][f][e] = sum_k xs[r][f][k] * W[k][e] ----
    // 256 threads: 2 f-rows x 4 e-cols x 2 batch rows each; every w float4
    // feeds 4 FMA4s (W SMEM traffic amortized over 2 batch rows).
    const int e0 = (tid & 15) * 4;
    const int f0 = (tid >> 4) * 2;
    {
        float4 a00 = make_float4(0.f, 0.f, 0.f, 0.f);
        float4 a01 = make_float4(0.f, 0.f, 0.f, 0.f);
        float4 a10 = make_float4(0.f, 0.f, 0.f, 0.f);
        float4 a11 = make_float4(0.f, 0.f, 0.f, 0.f);

        const float* xs0 = xs;
        const float* xs1 = xs + FF * EE;

        #pragma unroll 8
        for (int k = 0; k < EE; ++k) {
            const float4 w = *reinterpret_cast<const float4*>(&ws[k * EE + e0]);
            const float x00 = xs0[ f0      * EE + k];
            const float x01 = xs0[(f0 + 1) * EE + k];
            const float x10 = xs1[ f0      * EE + k];
            const float x11 = xs1[(f0 + 1) * EE + k];
            a00.x += x00 * w.x; a00.y += x00 * w.y; a00.z += x00 * w.z; a00.w += x00 * w.w;
            a01.x += x01 * w.x; a01.y += x01 * w.y; a01.z += x01 * w.z; a01.w += x01 * w.w;
            a10.x += x10 * w.x; a10.y += x10 * w.y; a10.z += x10 * w.z; a10.w += x10 * w.w;
            a11.x += x11 * w.x; a11.y += x11 * w.y; a11.z += x11 * w.z; a11.w += x11 * w.w;
        }

        *reinterpret_cast<float4*>(&xw[          f0      * EE + e0]) = a00;
        *reinterpret_cast<float4*>(&xw[         (f0 + 1) * EE + e0]) = a01;
        *reinterpret_cast<float4*>(&xw[FF * EE +  f0      * EE + e0]) = a10;
        *reinterpret_cast<float4*>(&xw[FF * EE + (f0 + 1) * EE + e0]) = a11;
    }

    __syncthreads();  // single barrier between compute and store

    // ---- store phase: out[b,p,e] = xw[i_p][e] * xs[j_p][e], both rows ----
    {
        const int v = tid & 15;
        const int g = tid >> 4;

        float4* og0 = reinterpret_cast<float4*>(out) + (size_t)b0 * NV4;

        store_rows(reinterpret_cast<const float4*>(xw),
                   reinterpret_cast<const float4*>(xs), og0, g, v);
        store_rows(reinterpret_cast<const float4*>(xw + FF * EE),
                   reinterpret_cast<const float4*>(xs + FF * EE), og0 + NV4, g, v);
    }
}

extern "C" void kernel_launch(void* const* d_in, const int* in_sizes, int n_in,
                              void* d_out, int out_size)
{
    const float* x = (const float*)d_in[0]; // [8192, 32, 64]
    const float* W = (const float*)d_in[1]; // [64, 64]
    float* out = (float*)d_out;             // [8192, 496, 64]
    (void)in_sizes; (void)n_in; (void)out_size;

    bilinear_kernel<<<BB / ROWS_PER_BLK, NTHREADS>>>(x, W, out);
}

// round 16
// speedup vs baseline: 1.0053x; 1.0053x over previous
#include <cuda_runtime.h>
#include <cstdint>
#include <cstddef>

// x:   [B=8192, F=32, E=64] f32
// W:   [E=64, E=64] f32
// out: [B, P=496, E=64] f32,  out[b,p,:] = (x[b,i_p,:] @ W) * x[b,j_p,:]
// (i_p, j_p) = triu_indices(32, k=1), row-major pair order.
//
// FINAL kernel (locked, R13 configuration; verified twice at 166.2-166.8us
// kernel / 170.0us e2e, HBM 6280-6301 GB/s):
//   - Problem is a pure HBM-write-roofline stream: 1.04 GB mandated f32
//     output vs 64 MB input and ~2 GF compute. 10 structurally distinct
//     configs (occ 23-93%, L1 63-93%, .cs/.wt/write-back stores, serial vs
//     interleaved issue, 256/512 threads, 1/2/4 rows per block, cp.async
//     pipelining) all converge at 6.15-6.30 TB/s => roofline reached.
// Structure: 2 batch rows/block (W SMEM traffic amortized 4-way in the
// matmul), dedicated xw buffer (single compute->store barrier), store phase
// with interleaved dual-row streams: 1 LDS.128 + 1 STG.128 per output
// float4, sequential 256B pair records per 16-lane group, streaming stores.

#define BB 8192
#define FF 32
#define EE 64
#define PP 496
#define NV4 (PP * (EE/4)) // 7936 float4 per batch row
#define NTHREADS 256
#define ROWS_PER_BLK 2

// pairs before row i: sum_{t<i} (31-t) = 31*i - i*(i-1)/2
__device__ __forceinline__ int rowstart(int i) {
    return 31 * i - (i * (i - 1)) / 2;
}

__device__ __forceinline__ float4 fmul4(float4 a, float4 c) {
    float4 r;
    r.x = a.x * c.x; r.y = a.y * c.y; r.z = a.z * c.z; r.w = a.w * c.w;
    return r;
}

// Store one batch row: 16 groups of 16 lanes; group g owns rows i1=g
// (pairs j=g+1..31) and i2=30-g (pairs j=31-g..31); g==15 owns only row 15
// (balanced: 32 pairs/group). Interleaved, fully unrolled dual streams:
// up to two independent LDS.128+STG.128 pairs per step -> deep store MLP,
// no loop-carried issue dependency.
__device__ __forceinline__ void store_rows(const float4* __restrict__ xw4,
                                           const float4* __restrict__ xs4,
                                           float4* __restrict__ og,
                                           int g, int v)
{
    const int i1 = g;
    const int i2 = 30 - g;                   // g==15 -> i2==i1 (masked below)
    const bool two = (g < 15);

    const float4 a1 = xw4[i1 * 16 + v];
    const float4 a2 = xw4[i2 * 16 + v];

    float4* o1 = og + (ptrdiff_t)(rowstart(i1) - i1 - 1) * 16 + v;
    float4* o2 = og + (ptrdiff_t)(rowstart(i2) - i2 - 1) * 16 + v;

    #pragma unroll
    for (int j = 1; j < FF; ++j) {
        if (j > i1) {
            const float4 c = xs4[j * 16 + v];
            __stcs(o1 + j * 16, fmul4(a1, c));
        }
        if (two && j > i2) {
            const float4 c = xs4[j * 16 + v];
            __stcs(o2 + j * 16, fmul4(a2, c));
        }
    }
}

__global__ __launch_bounds__(NTHREADS)
void bilinear_kernel(const float* __restrict__ x,
                     const float* __restrict__ W,
                     float* __restrict__ out)
{
    // 48 KB smem; dedicated xw buffer -> single barrier between compute and
    // store. Measured: any occupancy >= ~25% saturates the HBM write stream.
    __shared__ float xs[ROWS_PER_BLK * FF * EE]; // 16 KB : x[b0], x[b0+1]
    __shared__ float ws[EE * EE];                // 16 KB : W
    __shared__ float xw[ROWS_PER_BLK * FF * EE]; // 16 KB : xw[0], xw[1]

    const int tid = threadIdx.x;
    const int b0  = blockIdx.x * ROWS_PER_BLK;

    // ---- load x rows (1024 float4) and W (1024 float4) into SMEM ----
    {
        const float4* xg = reinterpret_cast<const float4*>(x) + (size_t)b0 * (FF * EE / 4);
        float4* xs4 = reinterpret_cast<float4*>(xs);
        #pragma unroll
        for (int q = tid; q < ROWS_PER_BLK * FF * EE / 4; q += NTHREADS)
            xs4[q] = xg[q];

        const float4* wg = reinterpret_cast<const float4*>(W);
        float4* ws4 = reinterpret_cast<float4*>(ws);
        #pragma unroll
        for (int q = tid; q < EE * EE / 4; q += NTHREADS)
            ws4[q] = wg[q];
    }

    __syncthreads();

    // ---- matmul: xw[r][f][e] = sum_k xs[r][f][k] * W[k][e] ----
    // 256 threads: 2 f-rows x 4 e-cols x 2 batch rows each; every w float4
    // feeds 4 FMA4s (W SMEM traffic amortized over 2 batch rows).
    const int e0 = (tid & 15) * 4;
    const int f0 = (tid >> 4) * 2;
    {
        float4 a00 = make_float4(0.f, 0.f, 0.f, 0.f);
        float4 a01 = make_float4(0.f, 0.f, 0.f, 0.f);
        float4 a10 = make_float4(0.f, 0.f, 0.f, 0.f);
        float4 a11 = make_float4(0.f, 0.f, 0.f, 0.f);

        const float* xs0 = xs;
        const float* xs1 = xs + FF * EE;

        #pragma unroll 8
        for (int k = 0; k < EE; ++k) {
            const float4 w = *reinterpret_cast<const float4*>(&ws[k * EE + e0]);
            const float x00 = xs0[ f0      * EE + k];
            const float x01 = xs0[(f0 + 1) * EE + k];
            const float x10 = xs1[ f0      * EE + k];
            const float x11 = xs1[(f0 + 1) * EE + k];
            a00.x += x00 * w.x; a00.y += x00 * w.y; a00.z += x00 * w.z; a00.w += x00 * w.w;
            a01.x += x01 * w.x; a01.y += x01 * w.y; a01.z += x01 * w.z; a01.w += x01 * w.w;
            a10.x += x10 * w.x; a10.y += x10 * w.y; a10.z += x10 * w.z; a10.w += x10 * w.w;
            a11.x += x11 * w.x; a11.y += x11 * w.y; a11.z += x11 * w.z; a11.w += x11 * w.w;
        }

        *reinterpret_cast<float4*>(&xw[          f0      * EE + e0]) = a00;
        *reinterpret_cast<float4*>(&xw[         (f0 + 1) * EE + e0]) = a01;
        *reinterpret_cast<float4*>(&xw[FF * EE +  f0      * EE + e0]) = a10;
        *reinterpret_cast<float4*>(&xw[FF * EE + (f0 + 1) * EE + e0]) = a11;
    }

    __syncthreads();  // single barrier between compute and store

    // ---- store phase: out[b,p,e] = xw[i_p][e] * xs[j_p][e], both rows ----
    {
        const int v = tid & 15;
        const int g = tid >> 4;

        float4* og0 = reinterpret_cast<float4*>(out) + (size_t)b0 * NV4;

        store_rows(reinterpret_cast<const float4*>(xw),
                   reinterpret_cast<const float4*>(xs), og0, g, v);
        store_rows(reinterpret_cast<const float4*>(xw + FF * EE),
                   reinterpret_cast<const float4*>(xs + FF * EE), og0 + NV4, g, v);
    }
}

extern "C" void kernel_launch(void* const* d_in, const int* in_sizes, int n_in,
                              void* d_out, int out_size)
{
    const float* x = (const float*)d_in[0]; // [8192, 32, 64]
    const float* W = (const float*)d_in[1]; // [64, 64]
    float* out = (float*)d_out;             // [8192, 496, 64]
    (void)in_sizes; (void)n_in; (void)out_size;

    bilinear_kernel<<<BB / ROWS_PER_BLK, NTHREADS>>>(x, W, out);
}